// round 15
// baseline (speedup 1.0000x reference)
#include <cuda_runtime.h>
#include <cuda_fp16.h>
#include <cstdint>
#include <math.h>

#define NROWS 12288
#define DIM   128
#define BSZ   4096
#define BM    128
#define BN    128
#define NT    32           // 4096 / 128
#define SYMT  528          // 32*33/2
#define NBLK  (2*SYMT + 3*NT*NT)   // 4128 tiles
#define GRID  444          // 148 SMs x occ 3 (persistent, static schedule)

// ---- device scratch --------------------------------------------------------
__device__ __align__(16) uint8_t g_q[NROWS * DIM];  // normalized, e4m3 (x16)
__device__ float g_s[5][BSZ];   // row sums (xx, yy, xy, xz, yz)
__device__ float g_c[2][BSZ];   // col sums of xz, yz (== s_zx, s_zy)
__device__ float g_d[5][BSZ];   // diagonals

// ---- helpers ----------------------------------------------------------------
__device__ __forceinline__ uint32_t smem_u32(const void* p) {
    uint32_t a;
    asm("{ .reg .u64 t; cvta.to.shared.u64 t, %1; cvt.u32.u64 %0, t; }"
        : "=r"(a) : "l"(p));
    return a;
}
__device__ __forceinline__ __half2 h2ex2(__half2 a) {
    uint32_t r, x = *(uint32_t*)&a;
    asm("ex2.approx.f16x2 %0, %1;" : "=r"(r) : "r"(x));
    return *(__half2*)&r;
}
__device__ __forceinline__ void cp16(uint32_t dst, const void* src) {
    asm volatile("cp.async.cg.shared.global [%0], [%1], 16;"
                 :: "r"(dst), "l"(src) : "memory");
}
__device__ __forceinline__ void cp_commit() {
    asm volatile("cp.async.commit_group;" ::: "memory");
}
template <int N>
__device__ __forceinline__ void cp_wait() {
    asm volatile("cp.async.wait_group %0;" :: "n"(N) : "memory");
}
__device__ __forceinline__ void ldsm4(uint32_t* r, uint32_t a) {
    asm volatile("ldmatrix.sync.aligned.m8n8.x4.shared.b16 {%0,%1,%2,%3}, [%4];"
                 : "=r"(r[0]), "=r"(r[1]), "=r"(r[2]), "=r"(r[3]) : "r"(a));
}
// fp8 MMA: m16n8k32, e4m3 inputs, f16 accumulate (packed f16x2 C)
__device__ __forceinline__ void mma16832f8(uint32_t* c, const uint32_t* a, const uint32_t* b) {
    asm volatile(
        "mma.sync.aligned.m16n8k32.row.col.f16.e4m3.e4m3.f16 "
        "{%0,%1}, {%2,%3,%4,%5}, {%6,%7}, {%0,%1};"
        : "+r"(c[0]), "+r"(c[1])
        : "r"(a[0]), "r"(a[1]), "r"(a[2]), "r"(a[3]), "r"(b[0]), "r"(b[1]));
}
__device__ __forceinline__ uint16_t e4m3x2(float hi, float lo) {
    uint16_t p;
    asm("cvt.rn.satfinite.e4m3x2.f32 %0, %1, %2;" : "=h"(p) : "f"(hi), "f"(lo));
    return p;   // low byte = lo, high byte = hi
}

// ---- normalize -> e4m3 (8 threads/row) + zero scratch ------------------------
__global__ void __launch_bounds__(256) normalize_kernel(const float* __restrict__ x,
                                                        float* __restrict__ out) {
    int t = blockIdx.x * 256 + threadIdx.x;
    if (t < 5 * BSZ)            ((float*)g_s)[t] = 0.0f;
    else if (t < 7 * BSZ)       ((float*)g_c)[t - 5 * BSZ] = 0.0f;
    if (t == 0) out[0] = 0.0f;            // loss kernel accumulates atomically

    int row = blockIdx.x * 32 + (threadIdx.x >> 3);
    int sub = threadIdx.x & 7;
    const float4* xp = (const float4*)(x + (size_t)row * DIM + sub * 16);
    float4 a = xp[0], b = xp[1], c = xp[2], d = xp[3];
    float ss = fmaf(a.x,a.x, fmaf(a.y,a.y, fmaf(a.z,a.z, a.w*a.w)))
             + fmaf(b.x,b.x, fmaf(b.y,b.y, fmaf(b.z,b.z, b.w*b.w)))
             + fmaf(c.x,c.x, fmaf(c.y,c.y, fmaf(c.z,c.z, c.w*c.w)))
             + fmaf(d.x,d.x, fmaf(d.y,d.y, fmaf(d.z,d.z, d.w*d.w)));
    ss += __shfl_xor_sync(0xffffffffu, ss, 1);
    ss += __shfl_xor_sync(0xffffffffu, ss, 2);
    ss += __shfl_xor_sync(0xffffffffu, ss, 4);
    // scale by 16 to keep elements out of e4m3 subnormal range
    float s = rsqrtf(fmaxf(ss, 1e-24f)) * 16.0f;

    uint32_t w0 = (uint32_t)e4m3x2(a.y*s, a.x*s) | ((uint32_t)e4m3x2(a.w*s, a.z*s) << 16);
    uint32_t w1 = (uint32_t)e4m3x2(b.y*s, b.x*s) | ((uint32_t)e4m3x2(b.w*s, b.z*s) << 16);
    uint32_t w2 = (uint32_t)e4m3x2(c.y*s, c.x*s) | ((uint32_t)e4m3x2(c.w*s, c.z*s) << 16);
    uint32_t w3 = (uint32_t)e4m3x2(d.y*s, d.x*s) | ((uint32_t)e4m3x2(d.w*s, d.z*s) << 16);
    *(uint4*)(g_q + (size_t)row * DIM + sub * 16) = make_uint4(w0, w1, w2, w3);
}

// ---- persistent GEMM, static schedule, cross-tile double buffer --------------
// dyn smem: buf0 A|B 32K, buf1 A|B 32K, rs 512, cs 512
#define SM_RS     65536
#define SM_CS     (65536 + 512)
#define SMEM_BYTES (65536 + 1024)

__device__ __forceinline__ void decode_tile(int tile, int& z, int& by, int& bx) {
    if (tile < 2 * SYMT) {
        z = tile < SYMT ? 0 : 1;
        int t = tile - z * SYMT, r = 0;
        while (t >= NT - r) { t -= NT - r; r++; }
        by = r; bx = r + t;                       // upper triangle incl diag
    } else {
        int t = tile - 2 * SYMT;
        z = 2 + t / (NT * NT); t %= NT * NT;
        by = t / NT; bx = t % NT;
    }
}

__global__ void __launch_bounds__(256, 3) gemm_kernel() {
    extern __shared__ char sbp[];
    const uint32_t sb = smem_u32(sbp);

    const int tid = threadIdx.x, wid = tid >> 5, lane = tid & 31;
    const int warp_m = wid >> 2, warp_n = wid & 3;      // 2 x 4 warp grid
    const int rowT = warp_m * 64, colT = warp_n * 32;
    const int lr16 = lane & 15, lcs = (lane >> 4) * 16;
    const int q = lane >> 2, p2 = (lane & 3) * 2;

    // Swizzled LDSM bases within a 32KB buffer; addr(k32) = addr(0) ^ (k32<<5);
    // buffer 1 adds +32768.
    uint32_t aAd[4], bAd[2];
    #pragma unroll
    for (int mt = 0; mt < 4; mt++) {
        uint32_t row = (uint32_t)(rowT + mt * 16 + lr16);
        aAd[mt] = sb + ((row * 128 + (uint32_t)lcs) ^ ((row & 7) << 4));
    }
    #pragma unroll
    for (int nb = 0; nb < 2; nb++) {
        uint32_t row = (uint32_t)(colT + nb * 16 + lr16);
        bAd[nb] = sb + 16384 + ((row * 128 + (uint32_t)lcs) ^ ((row & 7) << 4));
    }

    float* rs = (float*)(sbp + SM_RS);
    float* cs = (float*)(sbp + SM_CS);
    const __half2 SC2 = __float2half2_rn(14.4269504088896340f / 256.0f);
    const int aoffs[5] = {0, 1, 0, 0, 1};
    const int boffs[5] = {0, 1, 1, 2, 2};

    const int rowQ = tid >> 3, seg = tid & 7;
    // stage tile -> buffer buf (A at buf*32768, B at buf*32768+16384)
    auto stage = [&](int tile, int buf) {
        int z, by, bx;
        decode_tile(tile, z, by, bx);
        const char* Agp = (const char*)g_q + (size_t)(aoffs[z] * BSZ + by * BM) * DIM;
        const char* Bgp = (const char*)g_q + (size_t)(boffs[z] * BSZ + bx * BN) * DIM;
        uint32_t base = sb + (uint32_t)(buf << 15);
        #pragma unroll
        for (int it = 0; it < 4; it++) {
            int row = rowQ + it * 32;
            uint32_t off = (uint32_t)(row * 128 + seg * 16);
            uint32_t sw  = off ^ ((row & 7) << 4);
            cp16(base + sw, Agp + off);
            cp16(base + 16384 + sw, Bgp + off);
        }
        cp_commit();
    };

    // Static schedule: tiles blockIdx, blockIdx+GRID, ...
    const int t0 = blockIdx.x;
    if (t0 >= NBLK) return;

    stage(t0, 0);

    for (int tile = t0, i = 0; tile < NBLK; tile += GRID, i ^= 1) {
        const int nxt = tile + GRID;
        const bool hasNext = (nxt < NBLK);
        if (hasNext) stage(nxt, i ^ 1);

        int z, by, bx;
        decode_tile(tile, z, by, bx);
        const bool sym      = (z < 2);
        const bool needCol  = (z >= 3) || (sym && bx > by);
        const bool needDiag = (by == bx);

        if (tid < BM) { rs[tid] = 0.0f; cs[tid] = 0.0f; }

        uint32_t acc[4][4][2];
        #pragma unroll
        for (int ii = 0; ii < 4; ii++)
            #pragma unroll
            for (int j = 0; j < 4; j++) { acc[ii][j][0] = 0u; acc[ii][j][1] = 0u; }

        if (hasNext) cp_wait<1>(); else cp_wait<0>();
        __syncthreads();                        // B1: buf[i] ready, rs/cs zeroed

        // ---- mainloop: 4 k32 steps from buffer i -----------------------------
        const uint32_t bofs = (uint32_t)(i << 15);
        #pragma unroll
        for (int k32 = 0; k32 < 4; k32++) {
            const uint32_t kx = (uint32_t)k32 << 5;
            uint32_t af[4][4], bf[2][4];
            #pragma unroll
            for (int mt = 0; mt < 4; mt++) ldsm4(af[mt], (aAd[mt] + bofs) ^ kx);
            #pragma unroll
            for (int nb = 0; nb < 2; nb++) ldsm4(bf[nb], (bAd[nb] + bofs) ^ kx);
            #pragma unroll
            for (int mt = 0; mt < 4; mt++)
                #pragma unroll
                for (int nt = 0; nt < 4; nt++) {
                    uint32_t bb[2] = {bf[nt >> 1][nt & 1], bf[nt >> 1][(nt & 1) + 2]};
                    mma16832f8(acc[mt][nt], af[mt], bb);
                }
        }

        // ---- epilogue: f16x2 exp + reductions --------------------------------
        float* dd = g_d[z];
        const int grb = by * BM, gcb = bx * BN;
        float rp[8], cp_[8];
        #pragma unroll
        for (int ii = 0; ii < 8; ii++) { rp[ii] = 0.0f; cp_[ii] = 0.0f; }

        #pragma unroll
        for (int mt = 0; mt < 4; mt++)
            #pragma unroll
            for (int nt = 0; nt < 4; nt++) {
                __half2 q0 = h2ex2(__hmul2(*(__half2*)&acc[mt][nt][0], SC2));
                __half2 q1 = h2ex2(__hmul2(*(__half2*)&acc[mt][nt][1], SC2));
                float2 f0 = __half22float2(q0);
                float2 f1 = __half22float2(q1);
                rp[mt * 2 + 0] += f0.x + f0.y;
                rp[mt * 2 + 1] += f1.x + f1.y;
                cp_[nt * 2 + 0] += f0.x + f1.x;
                cp_[nt * 2 + 1] += f0.y + f1.y;
                if (needDiag) {
                    int r0 = rowT + mt * 16 + q, r1 = r0 + 8;
                    int c0 = colT + nt * 8 + p2;
                    if (r0 == c0)     dd[grb + r0] = f0.x;
                    if (r0 == c0 + 1) dd[grb + r0] = f0.y;
                    if (r1 == c0)     dd[grb + r1] = f1.x;
                    if (r1 == c0 + 1) dd[grb + r1] = f1.y;
                }
            }

        #pragma unroll
        for (int o = 1; o <= 2; o <<= 1)
            #pragma unroll
            for (int ii = 0; ii < 8; ii++) rp[ii] += __shfl_xor_sync(0xffffffffu, rp[ii], o);
        if ((lane & 3) == 0) {
            #pragma unroll
            for (int mt = 0; mt < 4; mt++) {
                atomicAdd(&rs[rowT + mt * 16 + q],     rp[mt * 2 + 0]);
                atomicAdd(&rs[rowT + mt * 16 + q + 8], rp[mt * 2 + 1]);
            }
        }
        if (needCol) {
            #pragma unroll
            for (int o = 4; o <= 16; o <<= 1)
                #pragma unroll
                for (int ii = 0; ii < 8; ii++) cp_[ii] += __shfl_xor_sync(0xffffffffu, cp_[ii], o);
            if (lane < 4) {
                #pragma unroll
                for (int nt = 0; nt < 4; nt++) {
                    atomicAdd(&cs[colT + nt * 8 + lane * 2],     cp_[nt * 2 + 0]);
                    atomicAdd(&cs[colT + nt * 8 + lane * 2 + 1], cp_[nt * 2 + 1]);
                }
            }
        }
        __syncthreads();                        // B2: rs/cs complete

        float* srow = g_s[z];
        if (tid < BM) {
            atomicAdd(&srow[grb + tid], rs[tid]);
            if (needCol) {
                float cv = cs[tid];
                int cloc = gcb + tid;
                if (z == 3)      atomicAdd(&g_c[0][cloc], cv);
                else if (z == 4) atomicAdd(&g_c[1][cloc], cv);
                else             atomicAdd(&srow[cloc], cv);  // symmetric fold
            }
        }
        __syncthreads();                        // B3: rs/cs + buf reads done
    }
}

// ---- final loss: 16 blocks x 256 threads, one row/thread, atomic combine ----
__global__ void __launch_bounds__(256) loss_kernel(float* __restrict__ out) {
    __shared__ float red[256];
    int i = blockIdx.x * 256 + threadIdx.x;
    float d0 = g_d[0][i], s0 = g_s[0][i];
    float d1 = g_d[1][i], s1 = g_s[1][i];
    float d2 = g_d[2][i], s2 = g_s[2][i];
    float d3 = g_d[3][i], s3 = g_s[3][i];
    float d4 = g_d[4][i], s4 = g_s[4][i];
    float c0 = g_c[0][i], c1 = g_c[1][i];
    float denom = (s2 - d2) + (s0 - d0) + (s1 - d1);
    float acc = -2.0f * __logf(d2 / denom)
                - __logf(d3 / (s3 - d3)) - __logf(d4 / (s4 - d4))
                - __logf(d3 / (c0 - d3)) - __logf(d4 / (c1 - d4));
    red[threadIdx.x] = acc;
    __syncthreads();
    for (int s = 128; s >= 32; s >>= 1) {
        if (threadIdx.x < s) red[threadIdx.x] += red[threadIdx.x + s];
        __syncthreads();
    }
    if (threadIdx.x < 32) {
        float v = red[threadIdx.x];
        #pragma unroll
        for (int o = 16; o; o >>= 1) v += __shfl_xor_sync(0xffffffffu, v, o);
        if (threadIdx.x == 0) atomicAdd(out, v * (1.0f / BSZ));
    }
}

// ---------------------------------------------------------------------------
extern "C" void kernel_launch(void* const* d_in, const int* in_sizes, int n_in,
                              void* d_out, int out_size) {
    const float* x = (const float*)d_in[0];
    (void)in_sizes; (void)n_in; (void)out_size;

    cudaFuncSetAttribute(gemm_kernel, cudaFuncAttributeMaxDynamicSharedMemorySize,
                         SMEM_BYTES);

    normalize_kernel<<<NROWS / 32, 256>>>(x, (float*)d_out);
    gemm_kernel<<<GRID, 256, SMEM_BYTES>>>();
    loss_kernel<<<BSZ / 256, 256>>>((float*)d_out);
}

// round 16
// speedup vs baseline: 1.1404x; 1.1404x over previous
#include <cuda_runtime.h>
#include <cuda_fp16.h>
#include <cstdint>
#include <math.h>

#define NROWS 12288
#define DIM   128
#define BSZ   4096
#define BM    128
#define BN    128
#define NT    32           // 4096 / 128
#define SYMT  528          // 32*33/2
#define NBLK  (2*SYMT + 3*NT*NT)   // 4128

// ---- device scratch --------------------------------------------------------
__device__ __align__(16) uint8_t g_q[NROWS * DIM];  // normalized, e4m3 (x16)
__device__ float g_s[5][BSZ];   // row sums (xx, yy, xy, xz, yz)
__device__ float g_c[2][BSZ];   // col sums of xz, yz (== s_zx, s_zy)
__device__ float g_d[5][BSZ];   // diagonals

// ---- helpers ----------------------------------------------------------------
__device__ __forceinline__ uint32_t smem_u32(const void* p) {
    uint32_t a;
    asm("{ .reg .u64 t; cvta.to.shared.u64 t, %1; cvt.u32.u64 %0, t; }"
        : "=r"(a) : "l"(p));
    return a;
}
__device__ __forceinline__ __half2 h2ex2(__half2 a) {
    uint32_t r, x = *(uint32_t*)&a;
    asm("ex2.approx.f16x2 %0, %1;" : "=r"(r) : "r"(x));
    return *(__half2*)&r;
}
__device__ __forceinline__ void cp16(uint32_t dst, const void* src) {
    asm volatile("cp.async.cg.shared.global [%0], [%1], 16;"
                 :: "r"(dst), "l"(src) : "memory");
}
__device__ __forceinline__ void cp_commit() {
    asm volatile("cp.async.commit_group;" ::: "memory");
}
template <int N>
__device__ __forceinline__ void cp_wait() {
    asm volatile("cp.async.wait_group %0;" :: "n"(N) : "memory");
}
__device__ __forceinline__ void ldsm4(uint32_t* r, uint32_t a) {
    asm volatile("ldmatrix.sync.aligned.m8n8.x4.shared.b16 {%0,%1,%2,%3}, [%4];"
                 : "=r"(r[0]), "=r"(r[1]), "=r"(r[2]), "=r"(r[3]) : "r"(a));
}
// fp8 MMA: m16n8k32, e4m3 inputs, f16 accumulate (packed f16x2 C)
__device__ __forceinline__ void mma16832f8(uint32_t* c, const uint32_t* a, const uint32_t* b) {
    asm volatile(
        "mma.sync.aligned.m16n8k32.row.col.f16.e4m3.e4m3.f16 "
        "{%0,%1}, {%2,%3,%4,%5}, {%6,%7}, {%0,%1};"
        : "+r"(c[0]), "+r"(c[1])
        : "r"(a[0]), "r"(a[1]), "r"(a[2]), "r"(a[3]), "r"(b[0]), "r"(b[1]));
}
__device__ __forceinline__ uint16_t e4m3x2(float hi, float lo) {
    uint16_t p;
    asm("cvt.rn.satfinite.e4m3x2.f32 %0, %1, %2;" : "=h"(p) : "f"(hi), "f"(lo));
    return p;   // low byte = lo, high byte = hi
}

// ---- normalize -> e4m3 (8 threads/row) + zero scratch ------------------------
__global__ void __launch_bounds__(256) normalize_kernel(const float* __restrict__ x,
                                                        float* __restrict__ out) {
    int t = blockIdx.x * 256 + threadIdx.x;
    if (t < 5 * BSZ)            ((float*)g_s)[t] = 0.0f;
    else if (t < 7 * BSZ)       ((float*)g_c)[t - 5 * BSZ] = 0.0f;
    if (t == 0) out[0] = 0.0f;            // loss kernel accumulates atomically

    int row = blockIdx.x * 32 + (threadIdx.x >> 3);
    int sub = threadIdx.x & 7;
    const float4* xp = (const float4*)(x + (size_t)row * DIM + sub * 16);
    float4 a = xp[0], b = xp[1], c = xp[2], d = xp[3];
    float ss = fmaf(a.x,a.x, fmaf(a.y,a.y, fmaf(a.z,a.z, a.w*a.w)))
             + fmaf(b.x,b.x, fmaf(b.y,b.y, fmaf(b.z,b.z, b.w*b.w)))
             + fmaf(c.x,c.x, fmaf(c.y,c.y, fmaf(c.z,c.z, c.w*c.w)))
             + fmaf(d.x,d.x, fmaf(d.y,d.y, fmaf(d.z,d.z, d.w*d.w)));
    ss += __shfl_xor_sync(0xffffffffu, ss, 1);
    ss += __shfl_xor_sync(0xffffffffu, ss, 2);
    ss += __shfl_xor_sync(0xffffffffu, ss, 4);
    // scale by 16 to keep elements out of e4m3 subnormal range
    float s = rsqrtf(fmaxf(ss, 1e-24f)) * 16.0f;

    uint32_t w0 = (uint32_t)e4m3x2(a.y*s, a.x*s) | ((uint32_t)e4m3x2(a.w*s, a.z*s) << 16);
    uint32_t w1 = (uint32_t)e4m3x2(b.y*s, b.x*s) | ((uint32_t)e4m3x2(b.w*s, b.z*s) << 16);
    uint32_t w2 = (uint32_t)e4m3x2(c.y*s, c.x*s) | ((uint32_t)e4m3x2(c.w*s, c.z*s) << 16);
    uint32_t w3 = (uint32_t)e4m3x2(d.y*s, d.x*s) | ((uint32_t)e4m3x2(d.w*s, d.z*s) << 16);
    *(uint4*)(g_q + (size_t)row * DIM + sub * 16) = make_uint4(w0, w1, w2, w3);
}

// ---- main GEMM + fused exp/reduce (PDL consumer) ------------------------------
// dyn smem: A 16K | B 16K | rs 512 | cs 512   (whole K=128 resident)
#define SM_A      0
#define SM_B      16384
#define SM_RS     32768
#define SM_CS     (32768 + 512)
#define SMEM_BYTES (32768 + 1024)

__global__ void __launch_bounds__(256, 3) gemm_kernel() {
    extern __shared__ char sbp[];
    const uint32_t sb = smem_u32(sbp);

    const int tid = threadIdx.x, wid = tid >> 5, lane = tid & 31;

    // ---- PRE-SYNC prologue: everything that doesn't read normalize output ---
    int idx = blockIdx.x;
    int z, by, bx;
    if (idx < 2 * SYMT) {
        z = idx < SYMT ? 0 : 1;
        int t = idx - z * SYMT, r = 0;
        while (t >= NT - r) { t -= NT - r; r++; }
        by = r; bx = r + t;                       // upper triangle incl diag
    } else {
        int t = idx - 2 * SYMT;
        z = 2 + t / (NT * NT); t %= NT * NT;
        by = t / NT; bx = t % NT;
    }
    const int aoffs[5] = {0, 1, 0, 0, 1};
    const int boffs[5] = {0, 1, 1, 2, 2};
    const bool sym      = (z < 2);
    const bool needCol  = (z >= 3) || (sym && bx > by);
    const bool needDiag = (by == bx);

    const char* Agp = (const char*)g_q + (size_t)(aoffs[z] * BSZ + by * BM) * DIM;
    const char* Bgp = (const char*)g_q + (size_t)(boffs[z] * BSZ + bx * BN) * DIM;

    float* rs = (float*)(sbp + SM_RS);
    float* cs = (float*)(sbp + SM_CS);
    if (tid < BM) { rs[tid] = 0.0f; cs[tid] = 0.0f; }

    const int warp_m = wid >> 2, warp_n = wid & 3;      // 2 x 4 warp grid
    const int rowT = warp_m * 64, colT = warp_n * 32;
    const int lr16 = lane & 15, lcs = (lane >> 4) * 16;

    // Precomputed swizzled LDSM bases; addr(k32) = addr(0) ^ (k32 << 5)
    uint32_t aAd[4], bAd[2];
    #pragma unroll
    for (int mt = 0; mt < 4; mt++) {
        uint32_t row = (uint32_t)(rowT + mt * 16 + lr16);
        aAd[mt] = sb + SM_A + ((row * 128 + (uint32_t)lcs) ^ ((row & 7) << 4));
    }
    #pragma unroll
    for (int nb = 0; nb < 2; nb++) {
        uint32_t row = (uint32_t)(colT + nb * 16 + lr16);
        bAd[nb] = sb + SM_B + ((row * 128 + (uint32_t)lcs) ^ ((row & 7) << 4));
    }

    uint32_t acc[4][4][2];   // packed f16x2 accumulators
    #pragma unroll
    for (int i = 0; i < 4; i++)
        #pragma unroll
        for (int j = 0; j < 4; j++) { acc[i][j][0] = 0u; acc[i][j][1] = 0u; }

    // ---- wait for normalize_kernel's output to be visible -------------------
    cudaGridDependencySynchronize();

    // ---- stage whole tiles: rows are 128B; swizzle XOR (row&7)<<4 ----------
    {
        int rowQ = tid >> 3, seg = tid & 7;      // 32 rows per iter, 8x16B segs
        #pragma unroll
        for (int it = 0; it < 4; it++) {
            int row = rowQ + it * 32;
            uint32_t off = (uint32_t)(row * 128 + seg * 16);
            uint32_t sw  = off ^ ((row & 7) << 4);
            cp16(sb + SM_A + sw, Agp + off);
            cp16(sb + SM_B + sw, Bgp + off);
        }
        cp_commit();
    }

    cp_wait<0>(); __syncthreads();

    // ---- mainloop: 4 k32 steps ----------------------------------------------
    #pragma unroll
    for (int k32 = 0; k32 < 4; k32++) {
        const uint32_t kx = (uint32_t)k32 << 5;
        uint32_t af[4][4], bf[2][4];
        #pragma unroll
        for (int mt = 0; mt < 4; mt++) ldsm4(af[mt], aAd[mt] ^ kx);
        #pragma unroll
        for (int nb = 0; nb < 2; nb++) ldsm4(bf[nb], bAd[nb] ^ kx);
        #pragma unroll
        for (int mt = 0; mt < 4; mt++)
            #pragma unroll
            for (int nt = 0; nt < 4; nt++) {
                uint32_t bb[2] = {bf[nt >> 1][nt & 1], bf[nt >> 1][(nt & 1) + 2]};
                mma16832f8(acc[mt][nt], af[mt], bb);
            }
    }

    // ---- epilogue: f16x2 exp + reductions ------------------------------------
    // accum = 256 * dot  (inputs scaled x16), so fold 1/256 into the constant
    const __half2 SC2 = __float2half2_rn(14.4269504088896340f / 256.0f);
    const int q = lane >> 2, p2 = (lane & 3) * 2;
    float* dd = g_d[z];
    const int grb = by * BM, gcb = bx * BN;

    float rp[8], cp_[8];
    #pragma unroll
    for (int i = 0; i < 8; i++) { rp[i] = 0.0f; cp_[i] = 0.0f; }

    #pragma unroll
    for (int mt = 0; mt < 4; mt++)
        #pragma unroll
        for (int nt = 0; nt < 4; nt++) {
            __half2 q0 = h2ex2(__hmul2(*(__half2*)&acc[mt][nt][0], SC2));
            __half2 q1 = h2ex2(__hmul2(*(__half2*)&acc[mt][nt][1], SC2));
            float2 f0 = __half22float2(q0);
            float2 f1 = __half22float2(q1);
            rp[mt * 2 + 0] += f0.x + f0.y;
            rp[mt * 2 + 1] += f1.x + f1.y;
            cp_[nt * 2 + 0] += f0.x + f1.x;
            cp_[nt * 2 + 1] += f0.y + f1.y;
            if (needDiag) {
                int r0 = rowT + mt * 16 + q, r1 = r0 + 8;
                int c0 = colT + nt * 8 + p2;
                if (r0 == c0)     dd[grb + r0] = f0.x;
                if (r0 == c0 + 1) dd[grb + r0] = f0.y;
                if (r1 == c0)     dd[grb + r1] = f1.x;
                if (r1 == c0 + 1) dd[grb + r1] = f1.y;
            }
        }

    // row sums: reduce over quad (lanes sharing t/4)
    #pragma unroll
    for (int o = 1; o <= 2; o <<= 1)
        #pragma unroll
        for (int i = 0; i < 8; i++) rp[i] += __shfl_xor_sync(0xffffffffu, rp[i], o);
    if ((lane & 3) == 0) {
        #pragma unroll
        for (int mt = 0; mt < 4; mt++) {
            atomicAdd(&rs[rowT + mt * 16 + q],     rp[mt * 2 + 0]);
            atomicAdd(&rs[rowT + mt * 16 + q + 8], rp[mt * 2 + 1]);
        }
    }
    // col sums: reduce over lanes sharing t%4
    if (needCol) {
        #pragma unroll
        for (int o = 4; o <= 16; o <<= 1)
            #pragma unroll
            for (int i = 0; i < 8; i++) cp_[i] += __shfl_xor_sync(0xffffffffu, cp_[i], o);
        if (lane < 4) {
            #pragma unroll
            for (int nt = 0; nt < 4; nt++) {
                atomicAdd(&cs[colT + nt * 8 + lane * 2],     cp_[nt * 2 + 0]);
                atomicAdd(&cs[colT + nt * 8 + lane * 2 + 1], cp_[nt * 2 + 1]);
            }
        }
    }
    __syncthreads();

    float* srow = g_s[z];
    if (tid < BM) {
        atomicAdd(&srow[grb + tid], rs[tid]);
        if (needCol) {
            float cv = cs[tid];
            int cloc = gcb + tid;
            if (z == 3)      atomicAdd(&g_c[0][cloc], cv);
            else if (z == 4) atomicAdd(&g_c[1][cloc], cv);
            else             atomicAdd(&srow[cloc], cv);  // symmetric fold
        }
    }
}

// ---- final loss (PDL consumer): 16 blocks x 256 threads ----------------------
__global__ void __launch_bounds__(256) loss_kernel(float* __restrict__ out) {
    __shared__ float red[256];
    int i = blockIdx.x * 256 + threadIdx.x;

    cudaGridDependencySynchronize();   // wait for gemm results

    float d0 = g_d[0][i], s0 = g_s[0][i];
    float d1 = g_d[1][i], s1 = g_s[1][i];
    float d2 = g_d[2][i], s2 = g_s[2][i];
    float d3 = g_d[3][i], s3 = g_s[3][i];
    float d4 = g_d[4][i], s4 = g_s[4][i];
    float c0 = g_c[0][i], c1 = g_c[1][i];
    float denom = (s2 - d2) + (s0 - d0) + (s1 - d1);
    float acc = -2.0f * __logf(d2 / denom)
                - __logf(d3 / (s3 - d3)) - __logf(d4 / (s4 - d4))
                - __logf(d3 / (c0 - d3)) - __logf(d4 / (c1 - d4));
    red[threadIdx.x] = acc;
    __syncthreads();
    for (int s = 128; s >= 32; s >>= 1) {
        if (threadIdx.x < s) red[threadIdx.x] += red[threadIdx.x + s];
        __syncthreads();
    }
    if (threadIdx.x < 32) {
        float v = red[threadIdx.x];
        #pragma unroll
        for (int o = 16; o; o >>= 1) v += __shfl_xor_sync(0xffffffffu, v, o);
        if (threadIdx.x == 0) atomicAdd(out, v * (1.0f / BSZ));
    }
}

// ---------------------------------------------------------------------------
extern "C" void kernel_launch(void* const* d_in, const int* in_sizes, int n_in,
                              void* d_out, int out_size) {
    const float* x = (const float*)d_in[0];
    (void)in_sizes; (void)n_in; (void)out_size;

    cudaFuncSetAttribute(gemm_kernel, cudaFuncAttributeMaxDynamicSharedMemorySize,
                         SMEM_BYTES);

    normalize_kernel<<<NROWS / 32, 256>>>(x, (float*)d_out);

    // gemm: programmatic dependent launch on normalize
    {
        cudaLaunchConfig_t cfg = {};
        cfg.gridDim = dim3(NBLK, 1, 1);
        cfg.blockDim = dim3(256, 1, 1);
        cfg.dynamicSmemBytes = SMEM_BYTES;
        cfg.stream = 0;
        cudaLaunchAttribute at[1];
        at[0].id = cudaLaunchAttributeProgrammaticStreamSerialization;
        at[0].val.programmaticStreamSerializationAllowed = 1;
        cfg.attrs = at;
        cfg.numAttrs = 1;
        cudaLaunchKernelEx(&cfg, gemm_kernel);
    }

    // loss: programmatic dependent launch on gemm
    {
        cudaLaunchConfig_t cfg = {};
        cfg.gridDim = dim3(BSZ / 256, 1, 1);
        cfg.blockDim = dim3(256, 1, 1);
        cfg.dynamicSmemBytes = 0;
        cfg.stream = 0;
        cudaLaunchAttribute at[1];
        at[0].id = cudaLaunchAttributeProgrammaticStreamSerialization;
        at[0].val.programmaticStreamSerializationAllowed = 1;
        cfg.attrs = at;
        cfg.numAttrs = 1;
        cudaLaunchKernelEx(&cfg, loss_kernel, (float*)d_out);
    }
}